// round 10
// baseline (speedup 1.0000x reference)
#include <cuda_runtime.h>

// PINO elasticity loss on the fixed structured G x G grid mesh.
// Shared-memory staged 7-point block-stencil: each 256-thread block stages a
// 64(j) x 16(i) node tile (+1 halo) of u_pred and u_true into SMEM with
// coalesced batched loads, then computes 4 nodes/thread from SMEM with rolling
// register reuse. Interior uses the assembled constant stencil; boundary nodes
// use the masked per-triangle path. Single kernel, last-block finalize.

#define G 1024
#define NG (G * G)
#define NBLK 1024           // (G/64) * (G/16)
#define SW 66               // smem row stride (64 + 2 halo)

__device__ double g_acc[2];        // [0] sum unscaled (Rx^2+Ry^2), [1] sum unscaled energy
__device__ unsigned int g_count;   // finished-block counter (reset by last block)

__global__ __launch_bounds__(256) void k_main(const float2* __restrict__ up,
                                              const float2* __restrict__ ut,
                                              float* __restrict__ out) {
    const float NU = 0.3f;   // Poisson
    const float SH = 0.35f;  // (1-nu)/2
    const float TN = 0.6f;   // 2*nu

    __shared__ float2 sup[18 * SW];  // rows i0-1 .. i0+16, cols j0-1 .. j0+64
    __shared__ float2 sut[17 * SW];  // rows i0   .. i0+16, cols j0   .. j0+64

    int j0 = blockIdx.x << 6;   // 64-wide j tile
    int i0 = blockIdx.y << 4;   // 16-tall i tile
    int tid = threadIdx.x;

    // ---- Stage up tile: 18 rows x 66 cols, row/col clamped (ghosts are
    // garbage-but-valid; consumed only under masks). Coalesced per row run.
    #pragma unroll
    for (int t = 0; t < 5; t++) {
        int idx = tid + t * 256;
        if (idx < 18 * SW) {
            int r = idx / SW;
            int c = idx - r * SW;
            int gi = i0 - 1 + r;  gi = gi < 0 ? 0 : (gi > G - 1 ? G - 1 : gi);
            int gj = j0 - 1 + c;  gj = gj < 0 ? 0 : (gj > G - 1 ? G - 1 : gj);
            sup[idx] = up[(gi << 10) + gj];
        }
    }
    // ---- Stage ut tile: 17 rows x 66 cols (cols j0 .. j0+65, clamped).
    #pragma unroll
    for (int t = 0; t < 5; t++) {
        int idx = tid + t * 256;
        if (idx < 17 * SW) {
            int r = idx / SW;
            int c = idx - r * SW;
            int gi = i0 + r;      gi = gi > G - 1 ? G - 1 : gi;
            int gj = j0 + c;      gj = gj > G - 1 ? G - 1 : gj;
            sut[idx] = ut[(gi << 10) + gj];
        }
    }
    __syncthreads();

    // ---- Compute: thread -> j = j0+tj, i = i0 + tb*4 + k (k=0..3).
    int tj = tid & 63;
    int tb = tid >> 6;           // 0..3
    int j = j0 + tj;
    bool bj0 = (j > 0), bj1 = (j < G - 1);

    int b4 = tb << 2;
    // sup row of (i-1) at k: b4 + k ; center col = tj+1.
    const float2* PC = sup + tj + 1;  // center column
    const float2* PW = sup + tj;      // west column
    const float2* PE = sup + tj + 2;  // east column
    const float2* T0 = sut + tj;      // ut col j
    const float2* T1 = sut + tj + 1;  // ut col j+1

    // Rolling window init (k=0).
    float2 us = PC[b4 * SW];
    float2 u0 = PC[(b4 + 1) * SW];
    float2 uw = PW[(b4 + 1) * SW];
    float2 uQ = PE[b4 * SW];
    float2 ue = PE[(b4 + 1) * SW];
    float2 t0 = T0[b4 * SW];
    float2 te = T1[b4 * SW];

    float eq = 0.0f, en = 0.0f;

    #pragma unroll
    for (int k = 0; k < 4; k++) {
        int i = i0 + b4 + k;
        bool bi0 = (i > 0), bi1 = (i < G - 1);
        int rn = (b4 + k + 2) * SW;      // sup row of i+1

        float2 un  = PC[rn];
        float2 uP  = PW[rn];             // (i+1, j-1)
        float2 uen = PE[rn];             // (i+1, j+1); also next ue
        float2 tn  = T0[(b4 + k + 1) * SW];
        float2 tq  = T1[(b4 + k + 1) * SW];

        if (bi0 & bi1 & bj0 & bj1) {
            // Assembled interior stencil (unscaled; true R = (0.5/0.91)*this).
            float sxns = un.x + us.x, syns = un.y + us.y;
            float sxew = ue.x + uw.x, syew = ue.y + uw.y;
            float spqx = uP.x + uQ.x, spqy = uP.y + uQ.y;
            float Rx = 5.4f * u0.x + 1.3f * u0.y
                     - 2.0f  * sxns - 0.65f * syns
                     - 0.7f  * sxew - 0.65f * syew
                     + 0.65f * spqy;
            float Ry = 1.3f * u0.x + 5.4f * u0.y
                     - 0.65f * sxns - 0.7f  * syns
                     - 0.65f * sxew - 2.0f  * syew
                     + 0.65f * spqx;
            eq += Rx * Rx + Ry * Ry;
        } else {
            // Boundary: masked sum over the up-to-6 incident triangles.
            float Rx = 0.0f, Ry = 0.0f;
            float e0, e1, e2, s0, s1, s2;
            if (bi1 && bj1) {  // T1: tri1(i,j)   a=u0, b=ue, c=un
                e0 = un.x - u0.x; e1 = ue.y - u0.y; e2 = (ue.x - u0.x) + (un.y - u0.y);
                s0 = e0 + NU * e1; s1 = NU * e0 + e1; s2 = SH * e2;
                Rx -= s0 + s2; Ry -= s1 + s2;
            }
            if (bi1 && bj0) {  // T2: tri1(i,j-1) a=uw, b=u0, c=uP
                e0 = uP.x - uw.x; e1 = u0.y - uw.y; e2 = (u0.x - uw.x) + (uP.y - uw.y);
                Rx += SH * e2; Ry += NU * e0 + e1;
            }
            if (bi0 && bj1) {  // T3: tri1(i-1,j) a=us, b=uQ, c=u0
                e0 = u0.x - us.x; e1 = uQ.y - us.y; e2 = (uQ.x - us.x) + (u0.y - us.y);
                Rx += e0 + NU * e1; Ry += SH * e2;
            }
            if (bi1 && bj0) {  // T4: tri2(i,j-1) b=u0, d=un, c=uP
                e0 = un.x - u0.x; e1 = un.y - uP.y; e2 = -u0.y + un.x + un.y - uP.x;
                Rx -= e0 + NU * e1; Ry -= SH * e2;
            }
            if (bi0 && bj0) {  // T5: tri2(i-1,j-1) b=us, d=u0, c=uw
                e0 = u0.x - us.x; e1 = u0.y - uw.y; e2 = -us.y + u0.x + u0.y - uw.x;
                s0 = e0 + NU * e1; s1 = NU * e0 + e1; s2 = SH * e2;
                Rx += s0 + s2; Ry += s1 + s2;
            }
            if (bi0 && bj1) {  // T6: tri2(i-1,j) b=uQ, d=ue, c=u0
                e0 = ue.x - uQ.x; e1 = ue.y - u0.y; e2 = -uQ.y + ue.x + ue.y - u0.x;
                Rx -= SH * e2; Ry -= NU * e0 + e1;
            }
            eq += Rx * Rx + Ry * Ry;
        }

        // Energy for cell (i,j): corners a=(i,j), b=(i,j+1), c=(i+1,j),
        // d=(i+1,j+1) on u_err = u_pred - u_true.
        if (bi1 && bj1) {
            float ax = u0.x - t0.x,  ay = u0.y - t0.y;
            float bx = ue.x - te.x,  by = ue.y - te.y;
            float cx = un.x - tn.x,  cy = un.y - tn.y;
            float dx = uen.x - tq.x, dy = uen.y - tq.y;
            float e0 = cx - ax;
            float e1 = by - ay;
            float e2 = (bx - ax) + (cy - ay);
            en += e0 * e0 + e1 * e1 + TN * e0 * e1 + SH * e2 * e2;
            e0 = dx - bx;
            e1 = dy - cy;
            e2 = -by + dx + dy - cx;
            en += e0 * e0 + e1 * e1 + TN * e0 * e1 + SH * e2 * e2;
        }

        // Roll the window up one row.
        us = u0; u0 = un;
        uw = uP; uQ = ue; ue = uen;
        t0 = tn; te = tq;
    }

    // Block reduction (8 warps), then one double-atomic pair per block.
    #pragma unroll
    for (int o = 16; o > 0; o >>= 1) {
        eq += __shfl_xor_sync(0xFFFFFFFFu, eq, o);
        en += __shfl_xor_sync(0xFFFFFFFFu, en, o);
    }
    __shared__ float s_eq[8], s_en[8];
    int w = tid >> 5, l = tid & 31;
    if (l == 0) { s_eq[w] = eq; s_en[w] = en; }
    __syncthreads();
    if (tid == 0) {
        float teq = 0.0f, ten = 0.0f;
        #pragma unroll
        for (int r = 0; r < 8; r++) { teq += s_eq[r]; ten += s_en[r]; }
        atomicAdd(&g_acc[0], (double)teq);
        atomicAdd(&g_acc[1], (double)ten);
        __threadfence();
        unsigned int done = atomicAdd(&g_count, 1u);
        if (done == NBLK - 1) {
            // Last block: finalize and reset for the next graph replay.
            const double K = 0.5 / 0.91;               // 0.5 * 1/(1-nu^2)
            double L_eq = (K * K) * g_acc[0] / (2.0 * (double)NG);
            double L_en = K * g_acc[1];                // total_area == 1 exactly
            out[0] = (float)(0.1 * L_eq + 0.1 * L_en);
            g_acc[0] = 0.0;
            g_acc[1] = 0.0;
            g_count = 0u;
        }
    }
}

extern "C" void kernel_launch(void* const* d_in, const int* in_sizes, int n_in,
                              void* d_out, int out_size) {
    const float2* up = (const float2*)d_in[0];
    const float2* ut = (const float2*)d_in[1];
    float* out = (float*)d_out;
    (void)in_sizes; (void)n_in; (void)out_size;

    dim3 grid(G / 64, G / 16);
    k_main<<<grid, 256>>>(up, ut, out);
}

// round 14
// speedup vs baseline: 1.0050x; 1.0050x over previous
#include <cuda_runtime.h>

// PINO elasticity loss on the fixed structured G x G grid mesh.
// SMEM-staged 7-point block stencil with packed f32x2 math (sm_103a FFMA2).
// 512 blocks x 2 tiles each (single balanced wave); 4 nodes/thread from SMEM
// with rolling reuse. Interior uses the assembled constant stencil; boundary
// nodes use the masked per-triangle path. Last-block finalize.

#define G 1024
#define NG (G * G)
#define NBLK 512            // blocks; each handles 2 tiles of 64(j) x 16(i)
#define SW 66               // smem row stride (64 + 2 halo)

typedef unsigned long long u64;

__device__ double g_acc[2];        // [0] sum unscaled (Rx^2+Ry^2), [1] sum unscaled energy
__device__ unsigned int g_count;   // finished-block counter (reset by last block)

__device__ __forceinline__ u64 PKC(float x, float y) {
    u64 r; asm("mov.b64 %0,{%1,%2};" : "=l"(r) : "f"(x), "f"(y)); return r;
}
__device__ __forceinline__ void UNPK(u64 a, float& x, float& y) {
    asm("mov.b64 {%0,%1},%2;" : "=f"(x), "=f"(y) : "l"(a));
}
__device__ __forceinline__ float2 F2(u64 a) {
    float2 v; UNPK(a, v.x, v.y); return v;
}
__device__ __forceinline__ u64 ADD2(u64 a, u64 b) {
    u64 r; asm("add.rn.f32x2 %0,%1,%2;" : "=l"(r) : "l"(a), "l"(b)); return r;
}
__device__ __forceinline__ u64 MUL2(u64 a, u64 b) {
    u64 r; asm("mul.rn.f32x2 %0,%1,%2;" : "=l"(r) : "l"(a), "l"(b)); return r;
}
__device__ __forceinline__ u64 FMA2(u64 a, u64 b, u64 c) {
    u64 r; asm("fma.rn.f32x2 %0,%1,%2,%3;" : "=l"(r) : "l"(a), "l"(b), "l"(c)); return r;
}
__device__ __forceinline__ u64 SWP(u64 a) {       // (hi, lo)
    u64 r; asm("{.reg .f32 l,h; mov.b64 {l,h},%1; mov.b64 %0,{h,l};}" : "=l"(r) : "l"(a)); return r;
}
__device__ __forceinline__ u64 MIXLH(u64 a, u64 b) {  // (a.lo, b.hi)
    u64 r; asm("{.reg .f32 al,ah,bl,bh; mov.b64 {al,ah},%1; mov.b64 {bl,bh},%2; mov.b64 %0,{al,bh};}"
               : "=l"(r) : "l"(a), "l"(b)); return r;
}
__device__ __forceinline__ u64 MIXHL(u64 a, u64 b) {  // (a.hi, b.lo)
    u64 r; asm("{.reg .f32 al,ah,bl,bh; mov.b64 {al,ah},%1; mov.b64 {bl,bh},%2; mov.b64 %0,{ah,bl};}"
               : "=l"(r) : "l"(a), "l"(b)); return r;
}

__global__ __launch_bounds__(256) void k_main(const float2* __restrict__ up,
                                              const float2* __restrict__ ut,
                                              float* __restrict__ out) {
    const float NU = 0.3f;   // Poisson
    const float SH = 0.35f;  // (1-nu)/2
    const float TN = 0.6f;   // 2*nu

    __shared__ float2 sup[18 * SW];  // rows i0-1 .. i0+16, cols j0-1 .. j0+64
    __shared__ float2 sut[17 * SW];  // rows i0   .. i0+16, cols j0   .. j0+64

    int tid = threadIdx.x;

    // Packed constants (hoisted).
    const u64 C54   = PKC(5.4f, 5.4f);
    const u64 C13   = PKC(1.3f, 1.3f);
    const u64 Cm20  = PKC(-2.0f, -2.0f);
    const u64 Cm065 = PKC(-0.65f, -0.65f);
    const u64 Cm07  = PKC(-0.7f, -0.7f);
    const u64 C065  = PKC(0.65f, 0.65f);
    const u64 Cm1   = PKC(-1.0f, -1.0f);

    float eq = 0.0f;
    u64 eqp = 0ull, enp = 0ull;
    float encr = 0.0f, ene2 = 0.0f;

    #pragma unroll 1
    for (int s = 0; s < 2; s++) {
        int tile = blockIdx.x + (s << 9);
        int j0 = (tile & 15) << 6;
        int i0 = (tile >> 4) << 4;

        // ---- Stage up tile: 18 x 66, row/col clamped (ghosts garbage-but-valid,
        // consumed only under masks).
        #pragma unroll
        for (int t = 0; t < 5; t++) {
            int idx = tid + t * 256;
            if (idx < 18 * SW) {
                int r = idx / SW;
                int c = idx - r * SW;
                int gi = i0 - 1 + r;  gi = gi < 0 ? 0 : (gi > G - 1 ? G - 1 : gi);
                int gj = j0 - 1 + c;  gj = gj < 0 ? 0 : (gj > G - 1 ? G - 1 : gj);
                sup[idx] = up[(gi << 10) + gj];
            }
        }
        // ---- Stage ut tile: 17 x 66.
        #pragma unroll
        for (int t = 0; t < 5; t++) {
            int idx = tid + t * 256;
            if (idx < 17 * SW) {
                int r = idx / SW;
                int c = idx - r * SW;
                int gi = i0 + r;  gi = gi > G - 1 ? G - 1 : gi;
                int gj = j0 + c;  gj = gj > G - 1 ? G - 1 : gj;
                sut[idx] = ut[(gi << 10) + gj];
            }
        }
        __syncthreads();

        // ---- Compute: thread -> j = j0+tj, i = i0 + tb*4 + k.
        int tj = tid & 63;
        int tb = tid >> 6;       // 0..3
        int j = j0 + tj;
        bool bj0 = (j > 0), bj1 = (j < G - 1);
        int b4 = tb << 2;

        const u64* PC = (const u64*)sup + tj + 1;
        const u64* PW = (const u64*)sup + tj;
        const u64* PE = (const u64*)sup + tj + 2;
        const u64* T0 = (const u64*)sut + tj;
        const u64* T1 = (const u64*)sut + tj + 1;

        u64 us = PC[b4 * SW];
        u64 u0 = PC[(b4 + 1) * SW];
        u64 uw = PW[(b4 + 1) * SW];
        u64 uQ = PE[b4 * SW];
        u64 ue = PE[(b4 + 1) * SW];
        u64 t0 = T0[b4 * SW];
        u64 te = T1[b4 * SW];

        #pragma unroll
        for (int k = 0; k < 4; k++) {
            int i = i0 + b4 + k;
            bool bi0 = (i > 0), bi1 = (i < G - 1);
            int rn = (b4 + k + 2) * SW;

            u64 un  = PC[rn];
            u64 uP  = PW[rn];                 // (i+1, j-1)
            u64 uen = PE[rn];                 // (i+1, j+1)
            u64 tn  = T0[(b4 + k + 1) * SW];
            u64 tq  = T1[(b4 + k + 1) * SW];

            if (bi0 & bi1 & bj0 & bj1) {
                // Packed interior stencil: lanes = (Rx, Ry), unscaled.
                u64 sns = ADD2(un, us);       // (sxns, syns)
                u64 sew = ADD2(ue, uw);       // (sxew, syew)
                u64 spq = ADD2(uP, uQ);       // (spqx, spqy)
                u64 P = MIXLH(sns, sew);      // (sxns, syew)
                u64 Q = MIXHL(sns, sew);      // (syns, sxew)
                u64 R = MUL2(u0, C54);
                R = FMA2(SWP(u0), C13, R);
                R = FMA2(P, Cm20, R);
                R = FMA2(Q, Cm065, R);
                R = FMA2(SWP(Q), Cm07, R);    // (sxew, syns)
                R = FMA2(SWP(P), Cm065, R);   // (syew, sxns)
                R = FMA2(SWP(spq), C065, R);  // (spqy, spqx)
                eqp = FMA2(R, R, eqp);
            } else {
                // Boundary: masked sum over the up-to-6 incident triangles (scalar).
                float2 fus = F2(us), fu0 = F2(u0), fun = F2(un);
                float2 fuw = F2(uw), fue = F2(ue), fuP = F2(uP), fuQ = F2(uQ);
                float Rx = 0.0f, Ry = 0.0f;
                float e0, e1, e2, s0, s1, s2;
                if (bi1 && bj1) {  // T1: tri1(i,j)   a=u0, b=ue, c=un
                    e0 = fun.x - fu0.x; e1 = fue.y - fu0.y; e2 = (fue.x - fu0.x) + (fun.y - fu0.y);
                    s0 = e0 + NU * e1; s1 = NU * e0 + e1; s2 = SH * e2;
                    Rx -= s0 + s2; Ry -= s1 + s2;
                }
                if (bi1 && bj0) {  // T2: tri1(i,j-1) a=uw, b=u0, c=uP
                    e0 = fuP.x - fuw.x; e1 = fu0.y - fuw.y; e2 = (fu0.x - fuw.x) + (fuP.y - fuw.y);
                    Rx += SH * e2; Ry += NU * e0 + e1;
                }
                if (bi0 && bj1) {  // T3: tri1(i-1,j) a=us, b=uQ, c=u0
                    e0 = fu0.x - fus.x; e1 = fuQ.y - fus.y; e2 = (fuQ.x - fus.x) + (fu0.y - fus.y);
                    Rx += e0 + NU * e1; Ry += SH * e2;
                }
                if (bi1 && bj0) {  // T4: tri2(i,j-1) b=u0, d=un, c=uP
                    e0 = fun.x - fu0.x; e1 = fun.y - fuP.y; e2 = -fu0.y + fun.x + fun.y - fuP.x;
                    Rx -= e0 + NU * e1; Ry -= SH * e2;
                }
                if (bi0 && bj0) {  // T5: tri2(i-1,j-1) b=us, d=u0, c=uw
                    e0 = fu0.x - fus.x; e1 = fu0.y - fuw.y; e2 = -fus.y + fu0.x + fu0.y - fuw.x;
                    s0 = e0 + NU * e1; s1 = NU * e0 + e1; s2 = SH * e2;
                    Rx += s0 + s2; Ry += s1 + s2;
                }
                if (bi0 && bj1) {  // T6: tri2(i-1,j) b=uQ, d=ue, c=u0
                    e0 = fue.x - fuQ.x; e1 = fue.y - fu0.y; e2 = -fuQ.y + fue.x + fue.y - fu0.x;
                    Rx -= SH * e2; Ry -= NU * e0 + e1;
                }
                eq += Rx * Rx + Ry * Ry;
            }

            // Energy for cell (i,j): a=(i,j), b=(i,j+1), c=(i+1,j), d=(i+1,j+1)
            // on u_err = u_pred - u_true, packed.
            if (bi1 && bj1) {
                u64 a = FMA2(t0, Cm1, u0);
                u64 b = FMA2(te, Cm1, ue);
                u64 c = FMA2(tn, Cm1, un);
                u64 d = FMA2(tq, Cm1, uen);
                u64 mcb = MIXLH(c, b);            // (cx, by)
                u64 mbc = MIXLH(b, c);            // (bx, cy)
                u64 e1p = FMA2(a, Cm1, mcb);      // tri1 (e0,e1) = (cx-ax, by-ay)
                u64 g   = FMA2(a, Cm1, mbc);      // (bx-ax, cy-ay)
                u64 e2p = FMA2(mbc, Cm1, d);      // tri2 (e0,e1) = (dx-bx, dy-cy)
                u64 h   = FMA2(mcb, Cm1, d);      // (dx-cx, dy-by)
                enp = FMA2(e1p, e1p, enp);
                enp = FMA2(e2p, e2p, enp);
                float gx, gy, hx, hy, x1, y1, x2, y2;
                UNPK(g, gx, gy); UNPK(h, hx, hy);
                UNPK(e1p, x1, y1); UNPK(e2p, x2, y2);
                float e2a = gx + gy, e2b = hx + hy;
                ene2 = fmaf(e2a, e2a, ene2);
                ene2 = fmaf(e2b, e2b, ene2);
                encr = fmaf(x1, y1, encr);
                encr = fmaf(x2, y2, encr);
            }

            // Roll the window up one row.
            us = u0; u0 = un;
            uw = uP; uQ = ue; ue = uen;
            t0 = tn; te = tq;
        }
        __syncthreads();  // before next tile's staging overwrites SMEM
    }

    // Combine packed accumulators.
    {
        float ax, ay; UNPK(eqp, ax, ay);
        eq += ax + ay;
    }
    float en;
    {
        float ax, ay; UNPK(enp, ax, ay);
        en = ax + ay + TN * encr + SH * ene2;
    }

    // Block reduction (8 warps), then one double-atomic pair per block.
    #pragma unroll
    for (int o = 16; o > 0; o >>= 1) {
        eq += __shfl_xor_sync(0xFFFFFFFFu, eq, o);
        en += __shfl_xor_sync(0xFFFFFFFFu, en, o);
    }
    __shared__ float s_eq[8], s_en[8];
    int w = tid >> 5, l = tid & 31;
    if (l == 0) { s_eq[w] = eq; s_en[w] = en; }
    __syncthreads();
    if (tid == 0) {
        float teq = 0.0f, ten = 0.0f;
        #pragma unroll
        for (int r = 0; r < 8; r++) { teq += s_eq[r]; ten += s_en[r]; }
        atomicAdd(&g_acc[0], (double)teq);
        atomicAdd(&g_acc[1], (double)ten);
        __threadfence();
        unsigned int done = atomicAdd(&g_count, 1u);
        if (done == NBLK - 1) {
            // Last block: finalize and reset for the next graph replay.
            const double K = 0.5 / 0.91;               // 0.5 * 1/(1-nu^2)
            double L_eq = (K * K) * g_acc[0] / (2.0 * (double)NG);
            double L_en = K * g_acc[1];                // total_area == 1 exactly
            out[0] = (float)(0.1 * L_eq + 0.1 * L_en);
            g_acc[0] = 0.0;
            g_acc[1] = 0.0;
            g_count = 0u;
        }
    }
}

extern "C" void kernel_launch(void* const* d_in, const int* in_sizes, int n_in,
                              void* d_out, int out_size) {
    const float2* up = (const float2*)d_in[0];
    const float2* ut = (const float2*)d_in[1];
    float* out = (float*)d_out;
    (void)in_sizes; (void)n_in; (void)out_size;

    k_main<<<NBLK, 256>>>(up, ut, out);
}

// round 16
// speedup vs baseline: 1.0545x; 1.0494x over previous
#include <cuda_runtime.h>

// PINO elasticity loss on the fixed structured G x G grid mesh.
// SMEM-staged 7-point block stencil, packed f32x2 math (sm_103a FFMA2).
// 1024 blocks x one 64(j) x 16(i) tile; division-free staging; interior
// blocks take a branch-free packed path, edge blocks the masked path.
// Last-block finalize.

#define G 1024
#define NG (G * G)
#define NBX 16
#define NBY 64
#define NBLK (NBX * NBY)
#define SW 66               // sup row stride (64 + 2 halo)
#define SWT 65              // sut row stride (64 + 1 east halo)

typedef unsigned long long u64;

__device__ double g_acc[2];        // [0] sum unscaled (Rx^2+Ry^2), [1] sum unscaled energy
__device__ unsigned int g_count;   // finished-block counter (reset by last block)

__device__ __forceinline__ u64 PKC(float x, float y) {
    u64 r; asm("mov.b64 %0,{%1,%2};" : "=l"(r) : "f"(x), "f"(y)); return r;
}
__device__ __forceinline__ void UNPK(u64 a, float& x, float& y) {
    asm("mov.b64 {%0,%1},%2;" : "=f"(x), "=f"(y) : "l"(a));
}
__device__ __forceinline__ float2 F2(u64 a) {
    float2 v; UNPK(a, v.x, v.y); return v;
}
__device__ __forceinline__ u64 ADD2(u64 a, u64 b) {
    u64 r; asm("add.rn.f32x2 %0,%1,%2;" : "=l"(r) : "l"(a), "l"(b)); return r;
}
__device__ __forceinline__ u64 MUL2(u64 a, u64 b) {
    u64 r; asm("mul.rn.f32x2 %0,%1,%2;" : "=l"(r) : "l"(a), "l"(b)); return r;
}
__device__ __forceinline__ u64 FMA2(u64 a, u64 b, u64 c) {
    u64 r; asm("fma.rn.f32x2 %0,%1,%2,%3;" : "=l"(r) : "l"(a), "l"(b), "l"(c)); return r;
}
__device__ __forceinline__ u64 SWP(u64 a) {       // (hi, lo)
    u64 r; asm("{.reg .f32 l,h; mov.b64 {l,h},%1; mov.b64 %0,{h,l};}" : "=l"(r) : "l"(a)); return r;
}
__device__ __forceinline__ u64 MIXLH(u64 a, u64 b) {  // (a.lo, b.hi)
    u64 r; asm("{.reg .f32 al,ah,bl,bh; mov.b64 {al,ah},%1; mov.b64 {bl,bh},%2; mov.b64 %0,{al,bh};}"
               : "=l"(r) : "l"(a), "l"(b)); return r;
}
__device__ __forceinline__ u64 MIXHL(u64 a, u64 b) {  // (a.hi, b.lo)
    u64 r; asm("{.reg .f32 al,ah,bl,bh; mov.b64 {al,ah},%1; mov.b64 {bl,bh},%2; mov.b64 %0,{ah,bl};}"
               : "=l"(r) : "l"(a), "l"(b)); return r;
}

__global__ __launch_bounds__(256) void k_main(const float2* __restrict__ up,
                                              const float2* __restrict__ ut,
                                              float* __restrict__ out) {
    const float NU = 0.3f;   // Poisson
    const float SH = 0.35f;  // (1-nu)/2
    const float TN = 0.6f;   // 2*nu

    __shared__ float2 sup[18 * SW];   // rows i0-1 .. i0+16, cols j0-1 .. j0+64
    __shared__ float2 sut[17 * SWT];  // rows i0   .. i0+16, cols j0   .. j0+64

    int tid = threadIdx.x;
    int j0 = (int)blockIdx.x << 6;
    int i0 = (int)blockIdx.y << 4;

    int c  = tid & 63;       // column within tile
    int r0 = tid >> 6;       // 0..3

    // ---- Stage sup main area (division-free): rows r0+4t, col c -> smem col c+1.
    #pragma unroll
    for (int t = 0; t < 5; t++) {
        int r = r0 + (t << 2);
        if (r < 18) {
            int gi = i0 - 1 + r;
            gi = gi < 0 ? 0 : (gi > G - 1 ? G - 1 : gi);
            sup[r * SW + c + 1] = up[(gi << 10) + j0 + c];
        }
    }
    // ---- sup halo columns (west col 0 = j0-1, east col 65 = j0+64), clamped.
    if (tid < 36) {
        int r = tid >> 1;
        int e = tid & 1;
        int gi = i0 - 1 + r;
        gi = gi < 0 ? 0 : (gi > G - 1 ? G - 1 : gi);
        int gj = e ? (j0 + 64 > G - 1 ? G - 1 : j0 + 64) : (j0 > 0 ? j0 - 1 : 0);
        sup[r * SW + (e ? 65 : 0)] = up[(gi << 10) + gj];
    }
    // ---- Stage sut main area: rows r0+4t, col c -> smem col c (global j0+c).
    #pragma unroll
    for (int t = 0; t < 5; t++) {
        int r = r0 + (t << 2);
        if (r < 17) {
            int gi = i0 + r;  gi = gi > G - 1 ? G - 1 : gi;
            sut[r * SWT + c] = ut[(gi << 10) + j0 + c];
        }
    }
    // ---- sut east halo col 64 (global j0+64), clamped.
    if (tid >= 64 && tid < 81) {
        int r = tid - 64;
        int gi = i0 + r;      gi = gi > G - 1 ? G - 1 : gi;
        int gj = j0 + 64;     gj = gj > G - 1 ? G - 1 : gj;
        sut[r * SWT + 64] = ut[(gi << 10) + gj];
    }
    __syncthreads();

    // Packed constants.
    const u64 C54   = PKC(5.4f, 5.4f);
    const u64 C13   = PKC(1.3f, 1.3f);
    const u64 Cm20  = PKC(-2.0f, -2.0f);
    const u64 Cm065 = PKC(-0.65f, -0.65f);
    const u64 Cm07  = PKC(-0.7f, -0.7f);
    const u64 C065  = PKC(0.65f, 0.65f);
    const u64 Cm1   = PKC(-1.0f, -1.0f);

    int tj = c;
    int b4 = r0 << 2;

    const u64* PC = (const u64*)sup + tj + 1;
    const u64* PW = (const u64*)sup + tj;
    const u64* PE = (const u64*)sup + tj + 2;
    const u64* T0 = (const u64*)sut + tj;
    const u64* T1 = (const u64*)sut + tj + 1;

    // Rolling window init (k=0; smem sup row r = global i0-1+r).
    u64 us = PC[b4 * SW];
    u64 u0 = PC[(b4 + 1) * SW];
    u64 uw = PW[(b4 + 1) * SW];
    u64 uQ = PE[b4 * SW];
    u64 ue = PE[(b4 + 1) * SW];
    u64 t0 = T0[b4 * SWT];
    u64 te = T1[b4 * SWT];

    float eq = 0.0f;
    u64 eqp = 0ull, enp = 0ull;
    float encr = 0.0f, ene2 = 0.0f;

    bool blk_int = (blockIdx.x > 0) & (blockIdx.x < NBX - 1) &
                   (blockIdx.y > 0) & (blockIdx.y < NBY - 1);

    if (blk_int) {
        // ---- Fast path: every node interior, every cell valid. No masks.
        #pragma unroll
        for (int k = 0; k < 4; k++) {
            int rn = (b4 + k + 2) * SW;
            u64 un  = PC[rn];
            u64 uP  = PW[rn];
            u64 uen = PE[rn];
            u64 tn  = T0[(b4 + k + 1) * SWT];
            u64 tq  = T1[(b4 + k + 1) * SWT];

            // Packed interior stencil: lanes = (Rx, Ry), unscaled.
            u64 sns = ADD2(un, us);
            u64 sew = ADD2(ue, uw);
            u64 spq = ADD2(uP, uQ);
            u64 P = MIXLH(sns, sew);      // (sxns, syew)
            u64 Q = MIXHL(sns, sew);      // (syns, sxew)
            u64 R = MUL2(u0, C54);
            R = FMA2(SWP(u0), C13, R);
            R = FMA2(P, Cm20, R);
            R = FMA2(Q, Cm065, R);
            R = FMA2(SWP(Q), Cm07, R);
            R = FMA2(SWP(P), Cm065, R);
            R = FMA2(SWP(spq), C065, R);
            eqp = FMA2(R, R, eqp);

            // Energy for cell (i,j), packed.
            u64 a  = FMA2(t0, Cm1, u0);
            u64 b  = FMA2(te, Cm1, ue);
            u64 cc = FMA2(tn, Cm1, un);
            u64 d  = FMA2(tq, Cm1, uen);
            u64 mcb = MIXLH(cc, b);           // (cx, by)
            u64 mbc = MIXLH(b, cc);           // (bx, cy)
            u64 e1p = FMA2(a, Cm1, mcb);      // (cx-ax, by-ay)
            u64 g   = FMA2(a, Cm1, mbc);      // (bx-ax, cy-ay)
            u64 e2p = FMA2(mbc, Cm1, d);      // (dx-bx, dy-cy)
            u64 h   = FMA2(mcb, Cm1, d);      // (dx-cx, dy-by)
            enp = FMA2(e1p, e1p, enp);
            enp = FMA2(e2p, e2p, enp);
            float gx, gy, hx, hy, x1, y1, x2, y2;
            UNPK(g, gx, gy); UNPK(h, hx, hy);
            UNPK(e1p, x1, y1); UNPK(e2p, x2, y2);
            float e2a = gx + gy, e2b = hx + hy;
            ene2 = fmaf(e2a, e2a, ene2);
            ene2 = fmaf(e2b, e2b, ene2);
            encr = fmaf(x1, y1, encr);
            encr = fmaf(x2, y2, encr);

            us = u0; u0 = un;
            uw = uP; uQ = ue; ue = uen;
            t0 = tn; te = tq;
        }
    } else {
        // ---- Edge path: masked per-triangle boundary handling.
        int j = j0 + tj;
        bool bj0 = (j > 0), bj1 = (j < G - 1);
        #pragma unroll
        for (int k = 0; k < 4; k++) {
            int i = i0 + b4 + k;
            bool bi0 = (i > 0), bi1 = (i < G - 1);
            int rn = (b4 + k + 2) * SW;
            u64 un  = PC[rn];
            u64 uP  = PW[rn];
            u64 uen = PE[rn];
            u64 tn  = T0[(b4 + k + 1) * SWT];
            u64 tq  = T1[(b4 + k + 1) * SWT];

            if (bi0 & bi1 & bj0 & bj1) {
                u64 sns = ADD2(un, us);
                u64 sew = ADD2(ue, uw);
                u64 spq = ADD2(uP, uQ);
                u64 P = MIXLH(sns, sew);
                u64 Q = MIXHL(sns, sew);
                u64 R = MUL2(u0, C54);
                R = FMA2(SWP(u0), C13, R);
                R = FMA2(P, Cm20, R);
                R = FMA2(Q, Cm065, R);
                R = FMA2(SWP(Q), Cm07, R);
                R = FMA2(SWP(P), Cm065, R);
                R = FMA2(SWP(spq), C065, R);
                eqp = FMA2(R, R, eqp);
            } else {
                float2 fus = F2(us), fu0 = F2(u0), fun = F2(un);
                float2 fuw = F2(uw), fue = F2(ue), fuP = F2(uP), fuQ = F2(uQ);
                float Rx = 0.0f, Ry = 0.0f;
                float e0, e1, e2, s0, s1, s2;
                if (bi1 && bj1) {  // T1: tri1(i,j)   a=u0, b=ue, c=un
                    e0 = fun.x - fu0.x; e1 = fue.y - fu0.y; e2 = (fue.x - fu0.x) + (fun.y - fu0.y);
                    s0 = e0 + NU * e1; s1 = NU * e0 + e1; s2 = SH * e2;
                    Rx -= s0 + s2; Ry -= s1 + s2;
                }
                if (bi1 && bj0) {  // T2: tri1(i,j-1) a=uw, b=u0, c=uP
                    e0 = fuP.x - fuw.x; e1 = fu0.y - fuw.y; e2 = (fu0.x - fuw.x) + (fuP.y - fuw.y);
                    Rx += SH * e2; Ry += NU * e0 + e1;
                }
                if (bi0 && bj1) {  // T3: tri1(i-1,j) a=us, b=uQ, c=u0
                    e0 = fu0.x - fus.x; e1 = fuQ.y - fus.y; e2 = (fuQ.x - fus.x) + (fu0.y - fus.y);
                    Rx += e0 + NU * e1; Ry += SH * e2;
                }
                if (bi1 && bj0) {  // T4: tri2(i,j-1) b=u0, d=un, c=uP
                    e0 = fun.x - fu0.x; e1 = fun.y - fuP.y; e2 = -fu0.y + fun.x + fun.y - fuP.x;
                    Rx -= e0 + NU * e1; Ry -= SH * e2;
                }
                if (bi0 && bj0) {  // T5: tri2(i-1,j-1) b=us, d=u0, c=uw
                    e0 = fu0.x - fus.x; e1 = fu0.y - fuw.y; e2 = -fus.y + fu0.x + fu0.y - fuw.x;
                    s0 = e0 + NU * e1; s1 = NU * e0 + e1; s2 = SH * e2;
                    Rx += s0 + s2; Ry += s1 + s2;
                }
                if (bi0 && bj1) {  // T6: tri2(i-1,j) b=uQ, d=ue, c=u0
                    e0 = fue.x - fuQ.x; e1 = fue.y - fu0.y; e2 = -fuQ.y + fue.x + fue.y - fu0.x;
                    Rx -= SH * e2; Ry -= NU * e0 + e1;
                }
                eq += Rx * Rx + Ry * Ry;
            }

            if (bi1 && bj1) {
                u64 a  = FMA2(t0, Cm1, u0);
                u64 b  = FMA2(te, Cm1, ue);
                u64 cc = FMA2(tn, Cm1, un);
                u64 d  = FMA2(tq, Cm1, uen);
                u64 mcb = MIXLH(cc, b);
                u64 mbc = MIXLH(b, cc);
                u64 e1p = FMA2(a, Cm1, mcb);
                u64 g   = FMA2(a, Cm1, mbc);
                u64 e2p = FMA2(mbc, Cm1, d);
                u64 h   = FMA2(mcb, Cm1, d);
                enp = FMA2(e1p, e1p, enp);
                enp = FMA2(e2p, e2p, enp);
                float gx, gy, hx, hy, x1, y1, x2, y2;
                UNPK(g, gx, gy); UNPK(h, hx, hy);
                UNPK(e1p, x1, y1); UNPK(e2p, x2, y2);
                float e2a = gx + gy, e2b = hx + hy;
                ene2 = fmaf(e2a, e2a, ene2);
                ene2 = fmaf(e2b, e2b, ene2);
                encr = fmaf(x1, y1, encr);
                encr = fmaf(x2, y2, encr);
            }

            us = u0; u0 = un;
            uw = uP; uQ = ue; ue = uen;
            t0 = tn; te = tq;
        }
    }

    // Combine packed accumulators.
    {
        float ax, ay; UNPK(eqp, ax, ay);
        eq += ax + ay;
    }
    float en;
    {
        float ax, ay; UNPK(enp, ax, ay);
        en = ax + ay + TN * encr + SH * ene2;
    }

    // Block reduction (8 warps), then one double-atomic pair per block.
    #pragma unroll
    for (int o = 16; o > 0; o >>= 1) {
        eq += __shfl_xor_sync(0xFFFFFFFFu, eq, o);
        en += __shfl_xor_sync(0xFFFFFFFFu, en, o);
    }
    __shared__ float s_eq[8], s_en[8];
    int w = tid >> 5, l = tid & 31;
    if (l == 0) { s_eq[w] = eq; s_en[w] = en; }
    __syncthreads();
    if (tid == 0) {
        float teq = 0.0f, ten = 0.0f;
        #pragma unroll
        for (int r = 0; r < 8; r++) { teq += s_eq[r]; ten += s_en[r]; }
        atomicAdd(&g_acc[0], (double)teq);
        atomicAdd(&g_acc[1], (double)ten);
        __threadfence();
        unsigned int done = atomicAdd(&g_count, 1u);
        if (done == NBLK - 1) {
            // Last block: finalize and reset for the next graph replay.
            const double K = 0.5 / 0.91;               // 0.5 * 1/(1-nu^2)
            double L_eq = (K * K) * g_acc[0] / (2.0 * (double)NG);
            double L_en = K * g_acc[1];                // total_area == 1 exactly
            out[0] = (float)(0.1 * L_eq + 0.1 * L_en);
            g_acc[0] = 0.0;
            g_acc[1] = 0.0;
            g_count = 0u;
        }
    }
}

extern "C" void kernel_launch(void* const* d_in, const int* in_sizes, int n_in,
                              void* d_out, int out_size) {
    const float2* up = (const float2*)d_in[0];
    const float2* ut = (const float2*)d_in[1];
    float* out = (float*)d_out;
    (void)in_sizes; (void)n_in; (void)out_size;

    dim3 grid(NBX, NBY);
    k_main<<<grid, 256>>>(up, ut, out);
}